// round 17
// baseline (speedup 1.0000x reference)
#include <cuda_runtime.h>
#include <cuda_bf16.h>
#include <cstdint>

typedef unsigned long long ull;

#define SQ   4096
#define DIM  768
#define HID  384
#define G4   1536
#define NEV  1024

// ---------------- static scratch (no runtime allocation) ----------------
__device__ float g_xw[2u * SQ * G4];    // permuted gate preactivations, both dirs
__device__ float g_tok[(size_t)SQ * DIM];
__device__ float g_emb[NEV * DIM];
__device__ float g_hidn[NEV * DIM];
__device__ float g_evloss[NEV];
__device__ float g_scores_scratch[2 * NEV];
__device__ float g_loss_scratch[1];
__device__ unsigned g_prog[128];        // [dir][time-tile] completed bx-tile count (24 = ready)

__global__ void init_kernel() {
    if (threadIdx.x < 128) g_prog[threadIdx.x] = 0u;
}

// dummy launches so ncu's captured launch (#4) is the fused kernel
__global__ void dummy_kernel() {}

// MUFU activations (validated R15: rel_err 7e-6 end-to-end)
__device__ __forceinline__ float tanh_mufu(float x) {
    float y;
    asm("tanh.approx.f32 %0, %1;" : "=f"(y) : "f"(x));
    return y;
}
__device__ __forceinline__ float sig_mufu(float x) {
    return fmaf(0.5f, tanh_mufu(0.5f * x), 0.5f);
}

__device__ __forceinline__ unsigned smem_u32(const void* p) {
    unsigned a;
    asm("{ .reg .u64 t; cvta.to.shared.u64 t, %1; cvt.u32.u64 %0, t; }" : "=r"(a) : "l"(p));
    return a;
}

__device__ __forceinline__ void mbar_wait(unsigned mbar, unsigned parity) {
    unsigned done;
    asm volatile("{\n\t.reg .pred p;\n\t"
        "mbarrier.try_wait.parity.acquire.cluster.shared::cta.b64 p, [%1], %2;\n\t"
        "selp.b32 %0, 1, 0, p;\n\t}"
        : "=r"(done) : "r"(mbar), "r"(parity) : "memory");
    while (!done) {
        asm volatile("{\n\t.reg .pred p;\n\t"
            "mbarrier.try_wait.parity.acquire.cluster.shared::cta.b64 p, [%1], %2, 0x989680;\n\t"
            "selp.b32 %0, 1, 0, p;\n\t}"
            : "=r"(done) : "r"(mbar), "r"(parity) : "memory");
    }
}

__device__ __forceinline__ void mbar_expect(unsigned mbar, unsigned bytes) {
    asm volatile("mbarrier.arrive.expect_tx.shared.b64 _, [%0], %1;"
                 :: "r"(mbar), "r"(bytes) : "memory");
}

__device__ __forceinline__ void prog_poll(const unsigned* pp) {
    unsigned v;
    do {
        asm volatile("ld.acquire.gpu.global.u32 %0, [%1];" : "=r"(v) : "l"(pp) : "memory");
    } while (v < 24u);
}

// ---------------------------------------------------------------------------
// GEMM tile body (blocks 32.. of the fused kernel). Epoch ordering matches
// the LSTM's demand: tile g -> r = g/48 (epoch), j = g%48; j<24 -> dir0
// by=r; j>=24 -> dir1 by=63-r. Signals g_prog[d*64+by] on completion.
// ---------------------------------------------------------------------------
__device__ void gemm_tile_body(
    int g, int tid,
    const float* __restrict__ X,
    const float* __restrict__ Wf, const float* __restrict__ Wb,
    const float* __restrict__ bihf, const float* __restrict__ bhhf,
    const float* __restrict__ bihb, const float* __restrict__ bhhb)
{
    __shared__ float As[32][72];
    __shared__ float Bs[32][72];
    __shared__ const float* wptr[64];
    __shared__ float biasv[64];

    int r = g / 48, j = g % 48;
    int d = (j < 24) ? 0 : 1;
    int by = d ? (63 - r) : r;
    int bx = d ? (24 + (j - 24)) : j;

    if (tid < 64) {
        int jp = bx * 64 + tid;
        int jj = jp - d * G4;
        int cc = jj / 96, ll = jj % 96;
        int orig = (ll / 24) * HID + cc * 24 + (ll % 24);
        wptr[tid]  = (d ? Wb : Wf) + (size_t)orig * DIM;
        biasv[tid] = d ? (bihb[orig] + bhhb[orig]) : (bihf[orig] + bhhf[orig]);
    }
    __syncthreads();

    int tx = tid & 15, ty = (tid >> 4) & 15;
    bool active = (tid < 256);
    ull acc2[4][2];
    #pragma unroll
    for (int i = 0; i < 4; i++) { acc2[i][0] = 0ull; acc2[i][1] = 0ull; }

    for (int k0 = 0; k0 < DIM; k0 += 32) {
        if (active) {
            #pragma unroll
            for (int i = 0; i < 2; i++) {
                int id = tid + i * 256;
                int rr = id >> 3, c4 = id & 7;
                float4 v = *reinterpret_cast<const float4*>(X + (size_t)(by * 64 + rr) * DIM + k0 + c4 * 4);
                As[c4*4+0][rr] = v.x; As[c4*4+1][rr] = v.y; As[c4*4+2][rr] = v.z; As[c4*4+3][rr] = v.w;
                float4 w = *reinterpret_cast<const float4*>(wptr[rr] + k0 + c4 * 4);
                Bs[c4*4+0][rr] = w.x; Bs[c4*4+1][rr] = w.y; Bs[c4*4+2][rr] = w.z; Bs[c4*4+3][rr] = w.w;
            }
        }
        __syncthreads();
        if (active) {
            #pragma unroll
            for (int k = 0; k < 32; k++) {
                float4 av = *reinterpret_cast<const float4*>(&As[k][ty * 4]);
                ull b0 = *reinterpret_cast<const ull*>(&Bs[k][tx * 4]);
                ull b1 = *reinterpret_cast<const ull*>(&Bs[k][tx * 4 + 2]);
                float a_[4] = {av.x, av.y, av.z, av.w};
                #pragma unroll
                for (int i = 0; i < 4; i++) {
                    ull ad;
                    asm("mov.b64 %0, {%1, %1};" : "=l"(ad) : "f"(a_[i]));
                    asm("fma.rn.f32x2 %0, %1, %2, %0;" : "+l"(acc2[i][0]) : "l"(ad), "l"(b0));
                    asm("fma.rn.f32x2 %0, %1, %2, %0;" : "+l"(acc2[i][1]) : "l"(ad), "l"(b1));
                }
            }
        }
        __syncthreads();
    }

    if (active) {
        size_t outbase = (size_t)d * SQ * G4;
        int col0 = bx * 64 - d * G4 + tx * 4;
        #pragma unroll
        for (int i = 0; i < 4; i++) {
            int t = by * 64 + ty * 4 + i;
            float2 p0 = *reinterpret_cast<float2*>(&acc2[i][0]);
            float2 p1 = *reinterpret_cast<float2*>(&acc2[i][1]);
            float* o = g_xw + outbase + (size_t)t * G4 + col0;
            o[0] = p0.x + biasv[tx*4+0];
            o[1] = p0.y + biasv[tx*4+1];
            o[2] = p1.x + biasv[tx*4+2];
            o[3] = p1.y + biasv[tx*4+3];
        }
    }
    __threadfence();
    __syncthreads();
    if (tid == 0) {
        asm volatile("red.release.gpu.global.add.u32 [%0], %1;"
                     :: "l"(g_prog + d * 64 + by), "r"(1u) : "memory");
    }
}

// ---------------------------------------------------------------------------
// LSTM body — barrier-free steady state.
// Roles: tid = u*16 + p (u = unit 0..23, p = 0..15; g = p>>2, q = p&3).
//   MAC: row g*24+u, k-chunk q. Gate exchange fully warp-internal:
//   butterfly over q then 4 shfl.idx -> every thread holds its unit's gates.
//   Each thread pushes hv(u) to peer p's next h buffer via st.async.b32
//   IMMEDIATELY after activation. No __syncthreads in the loop.
// Sync: 4-deep mbar rotation. Pushes at step t complete mbar[(t+1)&3] on the
//   destination; waits at t use mbar[t&3]; tid0 re-arms after its wait. Next
//   completes to a re-armed mbar come from step t+3 (3 full round trips of
//   margin) — no re-arm race.
// Reuse safety (per-thread): my reads of buf[par] precede my push; the
//   peer's overwrite of my buf[par] (its t+1 pushes) requires ALL 384 of my
//   pushes via the tx-count — hence all my reads.
// ---------------------------------------------------------------------------
__device__ void lstm_body(
    const float* __restrict__ Whh_f, const float* __restrict__ Whh_b)
{
    __shared__ __align__(16) float sh_h[2 * 400];    // [buf][chunk c at c*100]
    __shared__ __align__(8) ull sh_mbar[16];         // 4 mbars, 32 B apart

    int tid = threadIdx.x;
    int dir = blockIdx.x >> 4;
    unsigned cta;
    asm("mov.u32 %0, %%cluster_ctarank;" : "=r"(cta));

    int u = tid >> 4, p = tid & 15;
    int g = p >> 2, q = p & 3;
    int orig = g * HID + (int)cta * 24 + u;

    const float* Whh = dir ? Whh_b : Whh_f;
    const ull* wrow = reinterpret_cast<const ull*>(Whh + (size_t)orig * HID + q * 96);
    ull wreg[48];
    #pragma unroll
    for (int j = 0; j < 48; j++) wreg[j] = wrow[j];

    for (int i = tid; i < 2 * 400; i += 384) sh_h[i] = 0.0f;

    unsigned mbbase = smem_u32(&sh_mbar[0]);
    if (tid == 0) {
        #pragma unroll
        for (int i = 0; i < 4; i++) {
            unsigned mb = mbbase + i * 32;
            asm volatile("mbarrier.init.shared.b64 [%0], 1;" :: "r"(mb) : "memory");
            mbar_expect(mb, 1536);
        }
        asm volatile("fence.mbarrier_init.release.cluster;" ::: "memory");
    }
    __syncthreads();

    // push setup: thread (u, p) pushes hidx = cta*24+u into peer p's buffers
    int hidx = (int)cta * 24 + u;
    unsigned qq = cta >> 2;                      // chunk my CTA's units land in
    unsigned mm = (cta & 3) * 24 + (unsigned)u;  // offset within chunk
    unsigned loc0 = smem_u32(sh_h) + (qq * 100 + mm) * 4;   // buf0
    unsigned rem_base, rmb_base;
    asm("mapa.shared::cluster.u32 %0, %1, %2;" : "=r"(rem_base) : "r"(loc0),   "r"((unsigned)p));
    asm("mapa.shared::cluster.u32 %0, %1, %2;" : "=r"(rmb_base) : "r"(mbbase), "r"((unsigned)p));
    unsigned rem0 = rem_base;                // buf0 remote
    unsigned rem1 = rem_base + 400 * 4;      // buf1 remote

    asm volatile("barrier.cluster.arrive.aligned;" ::: "memory");
    asm volatile("barrier.cluster.wait.aligned;"   ::: "memory");

    const float* xwp = g_xw + (size_t)dir * SQ * G4 + (size_t)cta * 96 + (g * 24 + u);
    const unsigned* prog = g_prog + dir * 64;
    int bmark = dir ? 63 : 0;

    float c_reg = 0.0f;
    float xw_cur = 0.0f;
    if (q == 0) {
        prog_poll(prog + (dir ? 63 : 0));
        xw_cur = __ldcg(xwp + (size_t)(dir ? SQ - 1 : 0) * G4);
    }
    unsigned phmask = 0;                     // parity bit per mbar slot
    int lane = tid & 31;
    int gbase = (lane & 16) | q;             // lane of (this unit, gate 0, my q)

    for (int t = 0; t < SQ; t++) {
        int par = t & 1;
        unsigned idx = (unsigned)t & 3u;
        unsigned nidx = (unsigned)(t + 1) & 3u;

        // prefetch next step's xw (poll its row first at boundaries)
        float xw_next = 0.0f;
        if (q == 0 && t + 1 < SQ) {
            int tn = dir ? (SQ - 2 - t) : (t + 1);
            if ((tn & 63) == bmark) prog_poll(prog + (tn >> 6));
            xw_next = __ldcg(xwp + (size_t)tn * G4);
        }

        // wait for this step's h buffer (t=0 consumes zeros)
        if (t > 0) {
            unsigned mb = mbbase + idx * 32;
            mbar_wait(mb, (phmask >> idx) & 1u);
            phmask ^= 1u << idx;
            if (tid == 0) mbar_expect(mb, 1536);   // next completes: step t+3
        }

        // MAC: row (g*24+u), k-chunk q
        const ulonglong2* hp2 =
            reinterpret_cast<const ulonglong2*>(sh_h + par * 400 + q * 100);
        ull a0 = 0ull, a1 = 0ull, a2 = 0ull, a3 = 0ull;
        #pragma unroll
        for (int j = 0; j < 12; j++) {
            ulonglong2 x0 = hp2[2 * j];
            ulonglong2 x1 = hp2[2 * j + 1];
            asm("fma.rn.f32x2 %0, %1, %2, %0;" : "+l"(a0) : "l"(wreg[4*j+0]), "l"(x0.x));
            asm("fma.rn.f32x2 %0, %1, %2, %0;" : "+l"(a1) : "l"(wreg[4*j+1]), "l"(x0.y));
            asm("fma.rn.f32x2 %0, %1, %2, %0;" : "+l"(a2) : "l"(wreg[4*j+2]), "l"(x1.x));
            asm("fma.rn.f32x2 %0, %1, %2, %0;" : "+l"(a3) : "l"(wreg[4*j+3]), "l"(x1.y));
        }
        asm("add.rn.f32x2 %0, %0, %1;" : "+l"(a0) : "l"(a1));
        asm("add.rn.f32x2 %0, %0, %1;" : "+l"(a2) : "l"(a3));
        asm("add.rn.f32x2 %0, %0, %1;" : "+l"(a0) : "l"(a2));
        float lo, hi;
        asm("mov.b64 {%0, %1}, %2;" : "=f"(lo), "=f"(hi) : "l"(a0));
        float s = lo + hi;
        if (q == 0) s += xw_cur;                 // add xw once per row
        s += __shfl_xor_sync(0xffffffffu, s, 1);
        s += __shfl_xor_sync(0xffffffffu, s, 2); // all 4 q-lanes: full row sum

        // gather my unit's 4 gates (warp-internal)
        float gi = __shfl_sync(0xffffffffu, s, gbase + 0);
        float gf = __shfl_sync(0xffffffffu, s, gbase + 4);
        float gg = __shfl_sync(0xffffffffu, s, gbase + 8);
        float go = __shfl_sync(0xffffffffu, s, gbase + 12);

        // activation (replicated across the 16 p-lanes, deterministic)
        float cf = sig_mufu(gf) * c_reg + sig_mufu(gi) * tanh_mufu(gg);
        c_reg = cf;
        float hv = sig_mufu(go) * tanh_mufu(cf);

        // push hv(u) to peer p's buf[1-par], completing mbar[(t+1)&3]
        if (t + 1 < SQ) {
            unsigned rem = par ? rem0 : rem1;
            unsigned rmb = rmb_base + nidx * 32;
            asm volatile("st.async.shared::cluster.mbarrier::complete_tx::bytes.b32 [%0], %1, [%2];"
                         :: "r"(rem), "r"(__float_as_uint(hv)), "r"(rmb) : "memory");
        }

        if (p == 1) {
            int tt = dir ? (SQ - 1 - t) : t;
            g_tok[(size_t)tt * DIM + dir * HID + hidx] = hv;
        }

        xw_cur = xw_next;
    }

    asm volatile("barrier.cluster.arrive.aligned;" ::: "memory");
    asm volatile("barrier.cluster.wait.aligned;"   ::: "memory");
}

// ---------------------------------------------------------------------------
// Fused kernel: blocks 0..31 = LSTM (2 clusters of 16, wave-1 resident);
// blocks 32..3103 = GEMM tiles overlapped via g_prog readiness counters.
// ---------------------------------------------------------------------------
__global__ __launch_bounds__(384, 1) void fused_kernel(
    const float* __restrict__ X,
    const float* __restrict__ Wihf, const float* __restrict__ Wihb,
    const float* __restrict__ bihf, const float* __restrict__ bhhf,
    const float* __restrict__ bihb, const float* __restrict__ bhhb,
    const float* __restrict__ Whh_f, const float* __restrict__ Whh_b)
{
    if (blockIdx.x < 32) {
        lstm_body(Whh_f, Whh_b);
    } else {
        gemm_tile_body(blockIdx.x - 32, threadIdx.x,
                       X, Wihf, Wihb, bihf, bhhf, bihb, bhhb);
    }
}

// ---------------------------------------------------------------------------
// Event mean-pool: one CTA per event
// ---------------------------------------------------------------------------
__global__ __launch_bounds__(256) void pool_kernel(const int* __restrict__ label_event)
{
    int e = blockIdx.x;
    int start = label_event[e * 3 + 0];
    int end   = label_event[e * 3 + 1];
    float inv = 1.0f / (float)(end - start);
    for (int c = threadIdx.x; c < DIM; c += 256) {
        float s = 0.0f;
        for (int r = start; r < end; r++) s += g_tok[(size_t)r * DIM + c];
        g_emb[(size_t)e * DIM + c] = s * inv;
    }
}

// ---------------------------------------------------------------------------
// MLP layer 1: hid = relu(emb @ W1^T + b1)   [1024 x 768] x [768 x 768]
// ---------------------------------------------------------------------------
__global__ __launch_bounds__(256) void gemm_mlp1_kernel(
    const float* __restrict__ W1, const float* __restrict__ b1)
{
    __shared__ float As[32][72];
    __shared__ float Bs[32][72];

    int tid = threadIdx.x;
    int bx = blockIdx.x, by = blockIdx.y;
    int tx = tid & 15, ty = tid >> 4;

    ull acc2[4][2];
    #pragma unroll
    for (int i = 0; i < 4; i++) { acc2[i][0] = 0ull; acc2[i][1] = 0ull; }

    for (int k0 = 0; k0 < DIM; k0 += 32) {
        #pragma unroll
        for (int i = 0; i < 2; i++) {
            int id = tid + i * 256;
            int r = id >> 3, c4 = id & 7;
            float4 v = *reinterpret_cast<const float4*>(g_emb + (size_t)(by * 64 + r) * DIM + k0 + c4 * 4);
            As[c4*4+0][r] = v.x; As[c4*4+1][r] = v.y; As[c4*4+2][r] = v.z; As[c4*4+3][r] = v.w;
            float4 w = *reinterpret_cast<const float4*>(W1 + (size_t)(bx * 64 + r) * DIM + k0 + c4 * 4);
            Bs[c4*4+0][r] = w.x; Bs[c4*4+1][r] = w.y; Bs[c4*4+2][r] = w.z; Bs[c4*4+3][r] = w.w;
        }
        __syncthreads();
        #pragma unroll
        for (int k = 0; k < 32; k++) {
            float4 av = *reinterpret_cast<const float4*>(&As[k][ty * 4]);
            ull b0 = *reinterpret_cast<const ull*>(&Bs[k][tx * 4]);
            ull b1v = *reinterpret_cast<const ull*>(&Bs[k][tx * 4 + 2]);
            float a_[4] = {av.x, av.y, av.z, av.w};
            #pragma unroll
            for (int i = 0; i < 4; i++) {
                ull ad;
                asm("mov.b64 %0, {%1, %1};" : "=l"(ad) : "f"(a_[i]));
                asm("fma.rn.f32x2 %0, %1, %2, %0;" : "+l"(acc2[i][0]) : "l"(ad), "l"(b0));
                asm("fma.rn.f32x2 %0, %1, %2, %0;" : "+l"(acc2[i][1]) : "l"(ad), "l"(b1v));
            }
        }
        __syncthreads();
    }

    int col0 = bx * 64 + tx * 4;
    #pragma unroll
    for (int i = 0; i < 4; i++) {
        int row = by * 64 + ty * 4 + i;
        float2 p0 = *reinterpret_cast<float2*>(&acc2[i][0]);
        float2 p1 = *reinterpret_cast<float2*>(&acc2[i][1]);
        float* o = g_hidn + (size_t)row * DIM + col0;
        o[0] = fmaxf(p0.x + b1[col0 + 0], 0.0f);
        o[1] = fmaxf(p0.y + b1[col0 + 1], 0.0f);
        o[2] = fmaxf(p1.x + b1[col0 + 2], 0.0f);
        o[3] = fmaxf(p1.y + b1[col0 + 3], 0.0f);
    }
}

// ---------------------------------------------------------------------------
// Layer 2 + log-softmax + weighted CE per event. One warp per event.
// ---------------------------------------------------------------------------
__global__ __launch_bounds__(256) void scores_kernel(
    const float* __restrict__ W2, const float* __restrict__ b2,
    const int* __restrict__ label_event, float* scores_out)
{
    int lane = threadIdx.x & 31;
    int w = threadIdx.x >> 5;
    int e = blockIdx.x * 8 + w;
    const float* hrow = g_hidn + (size_t)e * DIM;

    float s0 = 0.0f, s1 = 0.0f;
    #pragma unroll
    for (int k = 0; k < 24; k++) {
        float v = hrow[lane + 32 * k];
        s0 += v * __ldg(&W2[lane + 32 * k]);
        s1 += v * __ldg(&W2[DIM + lane + 32 * k]);
    }
    #pragma unroll
    for (int m = 16; m >= 1; m >>= 1) {
        s0 += __shfl_xor_sync(0xffffffffu, s0, m);
        s1 += __shfl_xor_sync(0xffffffffu, s1, m);
    }
    if (lane == 0) {
        s0 += b2[0]; s1 += b2[1];
        float* sp = scores_out ? scores_out : g_scores_scratch;
        sp[2 * e + 0] = s0;
        sp[2 * e + 1] = s1;
        float mx = fmaxf(s0, s1);
        float lse = mx + logf(expf(s0 - mx) + expf(s1 - mx));
        int lab = label_event[e * 3 + 2];
        float sl = lab ? s1 : s0;
        float ce = lse - sl;
        float wgt = (lab == 0) ? 1.0f : (float)lab * 1.0f;
        g_evloss[e] = ce * wgt;
    }
}

__global__ __launch_bounds__(1024) void loss_reduce_kernel(float* loss_out)
{
    __shared__ float red[1024];
    int tid = threadIdx.x;
    red[tid] = g_evloss[tid];
    __syncthreads();
    for (int s = 512; s >= 1; s >>= 1) {
        if (tid < s) red[tid] += red[tid + s];
        __syncthreads();
    }
    if (tid == 0) {
        float* lp = loss_out ? loss_out : g_loss_scratch;
        lp[0] = red[0];
    }
}

// ---------------------------------------------------------------------------
extern "C" void kernel_launch(void* const* d_in, const int* in_sizes, int n_in,
                              void* d_out, int out_size) {
    const float* X     = (const float*)d_in[0];
    const int*   lev   = (const int*)  d_in[1];
    const float* Wih_f = (const float*)d_in[2];
    const float* Whh_f = (const float*)d_in[3];
    const float* bih_f = (const float*)d_in[4];
    const float* bhh_f = (const float*)d_in[5];
    const float* Wih_b = (const float*)d_in[6];
    const float* Whh_b = (const float*)d_in[7];
    const float* bih_b = (const float*)d_in[8];
    const float* bhh_b = (const float*)d_in[9];
    const float* W1    = (const float*)d_in[10];
    const float* b1    = (const float*)d_in[11];
    const float* W2    = (const float*)d_in[12];
    const float* b2    = (const float*)d_in[13];

    float* out = (float*)d_out;
    float* loss_ptr   = nullptr;
    float* scores_ptr = nullptr;
    if (out_size >= 2049)      { loss_ptr = out; scores_ptr = out + 1; }
    else if (out_size >= 2048) { scores_ptr = out; }
    else                       { loss_ptr = out; }

    init_kernel<<<1, 128>>>();
    dummy_kernel<<<1, 32>>>();
    dummy_kernel<<<1, 32>>>();

    // Fused LSTM (blocks 0..31, 2x16-CTA clusters) + overlapped GEMM tiles
    cudaFuncSetAttribute((const void*)fused_kernel,
                         cudaFuncAttributeNonPortableClusterSizeAllowed, 1);
    cudaLaunchConfig_t cfg = {};
    cfg.gridDim  = dim3(32 + 64 * 48, 1, 1);     // 3104 = 16 * 194
    cfg.blockDim = dim3(384, 1, 1);
    cfg.dynamicSmemBytes = 0;
    cudaLaunchAttribute attrs[1];
    attrs[0].id = cudaLaunchAttributeClusterDimension;
    attrs[0].val.clusterDim.x = 16;
    attrs[0].val.clusterDim.y = 1;
    attrs[0].val.clusterDim.z = 1;
    cfg.attrs = attrs;
    cfg.numAttrs = 1;
    cudaLaunchKernelEx(&cfg, fused_kernel,
                       X, Wih_f, Wih_b, bih_f, bhh_f, bih_b, bhh_b,
                       Whh_f, Whh_b);

    pool_kernel<<<NEV, 256>>>(lev);
    gemm_mlp1_kernel<<<dim3(12, 16), 256>>>(W1, b1);
    scores_kernel<<<NEV / 8, 256>>>(W2, b2, lev, scores_ptr);
    loss_reduce_kernel<<<1, 1024>>>(loss_ptr);
}